// round 1
// baseline (speedup 1.0000x reference)
#include <cuda_runtime.h>

#define B_  8
#define T_  2048
#define E_  1024
#define H_  128
#define BT_ (B_*T_)

// Scratch for projected q, k, v (8 MB each) — __device__ globals per alloc rules.
__device__ float g_q[BT_*H_];
__device__ float g_k[BT_*H_];
__device__ float g_v[BT_*H_];

// Packed dual fp32 FMA: d = a*b + d on two lanes (sm_100+ f32x2).
__device__ __forceinline__ void ffma2(float2& d, float a, float2 b) {
    asm("{\n\t"
        ".reg .b64 ra, rb, rd;\n\t"
        "mov.b64 ra, {%2, %2};\n\t"
        "mov.b64 rb, {%3, %4};\n\t"
        "mov.b64 rd, {%0, %1};\n\t"
        "fma.rn.f32x2 rd, ra, rb, rd;\n\t"
        "mov.b64 {%0, %1}, rd;\n\t"
        "}"
        : "+f"(d.x), "+f"(d.y)
        : "f"(a), "f"(b.x), "f"(b.y));
}

// ---------------------------------------------------------------------------
// Projection: out[r, c] = sum_k x[r, k] * W[k, c]  for W in {Wq, Wk, Wv}
// Tile: 64 rows x 128 cols, BK = 32. 256 threads: tx = tid&31 (4 cols each),
// ry = tid>>5 (8 rows each). blockIdx.y selects which of the 3 projections.
// ---------------------------------------------------------------------------
__global__ __launch_bounds__(256, 2)
void proj_kernel(const float* __restrict__ x, const float* __restrict__ Wq,
                 const float* __restrict__ Wk, const float* __restrict__ Wv)
{
    __shared__ float xs[64*32];     // x tile, row-major
    __shared__ float ws[32*128];    // W tile, row-major

    const float* W;
    float* outp;
    if (blockIdx.y == 0)      { W = Wq; outp = g_q; }
    else if (blockIdx.y == 1) { W = Wk; outp = g_k; }
    else                      { W = Wv; outp = g_v; }

    const int r0  = blockIdx.x * 64;
    const int tid = threadIdx.x;
    const int tx  = tid & 31;   // col group: c = tx*4 + jj
    const int ry  = tid >> 5;   // row group: r = ry*8 + ii

    float2 acc[8][2];
    #pragma unroll
    for (int i = 0; i < 8; i++) {
        acc[i][0] = make_float2(0.f, 0.f);
        acc[i][1] = make_float2(0.f, 0.f);
    }

    for (int k0 = 0; k0 < E_; k0 += 32) {
        // Load x tile: 64x32 = 512 float4, 2 per thread (coalesced).
        #pragma unroll
        for (int it = 0; it < 2; it++) {
            int fidx = it*256 + tid;
            int c4 = fidx & 7, r = fidx >> 3;
            *(float4*)(xs + r*32 + c4*4) =
                *(const float4*)(x + (r0 + r)*E_ + k0 + c4*4);
        }
        // Load W tile: 32x128 = 1024 float4, 4 per thread (coalesced).
        #pragma unroll
        for (int it = 0; it < 4; it++) {
            int fidx = it*256 + tid;
            int c4 = fidx & 31, kk = fidx >> 5;
            *(float4*)(ws + kk*128 + c4*4) =
                *(const float4*)(W + (k0 + kk)*H_ + c4*4);
        }
        __syncthreads();

        #pragma unroll 8
        for (int kk = 0; kk < 32; kk++) {
            float a[8];
            #pragma unroll
            for (int i = 0; i < 8; i++) a[i] = xs[(ry*8 + i)*32 + kk];  // warp-broadcast
            float4 bv = *(float4*)(ws + kk*128 + tx*4);                 // conflict-free
            float2 b0 = make_float2(bv.x, bv.y), b1 = make_float2(bv.z, bv.w);
            #pragma unroll
            for (int i = 0; i < 8; i++) {
                ffma2(acc[i][0], a[i], b0);
                ffma2(acc[i][1], a[i], b1);
            }
        }
        __syncthreads();
    }

    #pragma unroll
    for (int i = 0; i < 8; i++) {
        float4 o4 = make_float4(acc[i][0].x, acc[i][0].y, acc[i][1].x, acc[i][1].y);
        *(float4*)(outp + (r0 + ry*8 + i)*H_ + tx*4) = o4;
    }
}

// ---------------------------------------------------------------------------
// Causal flash attention. One CTA per (batch, 64-row q tile). 256 threads:
// tx = tid&15 (col groups), ry = tid>>4 (row groups). S-tile micro: 4x4/thread;
// O micro: 4 rows x 8 head-cols/thread. K is transposed into smem; P staged
// through smem for the PV GEMM. Only KV tiles j <= qi are visited.
// ---------------------------------------------------------------------------
__global__ __launch_bounds__(256, 1)
void attn_kernel(float* __restrict__ out)
{
    extern __shared__ float sm[];
    float* Qs  = sm;                 // [64][132]  (pad 4 -> conflict-free a-loads)
    float* Kts = Qs + 64*132;        // [128][64]  K transposed (k-major)
    float* Vs  = Kts + 128*64;       // [64][128]
    float* Ps  = Vs + 64*128;        // [64][68]   (pad 4)

    const int b   = blockIdx.y;
    const int qi  = (int)gridDim.x - 1 - (int)blockIdx.x;  // long blocks first
    const int tid = threadIdx.x;
    const int tx  = tid & 15;   // c = tx*4 + jj (S), h = tx*8 + jj (O)
    const int ry  = tid >> 4;   // r = ry*4 + ii

    // Load Q tile (rows qi*64 .. +64) into padded smem.
    const float* qb = g_q + (b*T_ + qi*64)*H_;
    #pragma unroll
    for (int it = 0; it < 8; it++) {
        int fidx = it*256 + tid;
        int c4 = fidx & 31, r = fidx >> 5;
        *(float4*)(Qs + r*132 + c4*4) = *(const float4*)(qb + r*H_ + c4*4);
    }

    float2 o[4][4];
    float m[4], l[4];
    #pragma unroll
    for (int i = 0; i < 4; i++) {
        m[i] = -1e30f; l[i] = 0.f;
        #pragma unroll
        for (int jp = 0; jp < 4; jp++) o[i][jp] = make_float2(0.f, 0.f);
    }

    __syncthreads();

    for (int j = 0; j <= qi; j++) {
        const float* kb = g_k + (b*T_ + j*64)*H_;
        const float* vb = g_v + (b*T_ + j*64)*H_;

        // K tile: load + transpose into Kts[k][c] (conflict-free smem stores).
        #pragma unroll
        for (int it = 0; it < 8; it++) {
            int fidx = it*256 + tid;
            int c = fidx & 63, k4 = fidx >> 6;
            float4 val = *(const float4*)(kb + c*H_ + k4*4);
            Kts[(k4*4 + 0)*64 + c] = val.x;
            Kts[(k4*4 + 1)*64 + c] = val.y;
            Kts[(k4*4 + 2)*64 + c] = val.z;
            Kts[(k4*4 + 3)*64 + c] = val.w;
        }
        // V tile: straight copy (coalesced).
        #pragma unroll
        for (int it = 0; it < 8; it++) {
            int fidx = it*256 + tid;
            int c4 = fidx & 31, r = fidx >> 5;
            *(float4*)(Vs + r*128 + c4*4) = *(const float4*)(vb + r*H_ + c4*4);
        }
        __syncthreads();

        // S = Q @ K^T  (64x64x128)
        float2 s2[4][2];
        #pragma unroll
        for (int i = 0; i < 4; i++) { s2[i][0] = make_float2(0.f,0.f); s2[i][1] = make_float2(0.f,0.f); }
        #pragma unroll 4
        for (int kk = 0; kk < 128; kk++) {
            float a[4];
            #pragma unroll
            for (int i = 0; i < 4; i++) a[i] = Qs[(ry*4 + i)*132 + kk];
            float4 bv = *(float4*)(Kts + kk*64 + tx*4);
            float2 b0 = make_float2(bv.x, bv.y), b1 = make_float2(bv.z, bv.w);
            #pragma unroll
            for (int i = 0; i < 4; i++) {
                ffma2(s2[i][0], a[i], b0);
                ffma2(s2[i][1], a[i], b1);
            }
        }

        // Online softmax over rows (each row owned by 16 consecutive lanes).
        const float scale = 0.088388347648318447f;   // 1/sqrt(128)
        const bool diag = (j == qi);
        #pragma unroll
        for (int i = 0; i < 4; i++) {
            float sv[4] = { s2[i][0].x*scale, s2[i][0].y*scale,
                            s2[i][1].x*scale, s2[i][1].y*scale };
            if (diag) {
                int rloc = ry*4 + i, cbase = tx*4;
                #pragma unroll
                for (int jj = 0; jj < 4; jj++)
                    if (cbase + jj > rloc) sv[jj] = -1e30f;
            }
            float mx = fmaxf(fmaxf(sv[0], sv[1]), fmaxf(sv[2], sv[3]));
            mx = fmaxf(mx, __shfl_xor_sync(0xffffffffu, mx, 1));
            mx = fmaxf(mx, __shfl_xor_sync(0xffffffffu, mx, 2));
            mx = fmaxf(mx, __shfl_xor_sync(0xffffffffu, mx, 4));
            mx = fmaxf(mx, __shfl_xor_sync(0xffffffffu, mx, 8));
            float mnew = fmaxf(m[i], mx);
            float corr = __expf(m[i] - mnew);
            float p0 = __expf(sv[0] - mnew), p1 = __expf(sv[1] - mnew);
            float p2 = __expf(sv[2] - mnew), p3 = __expf(sv[3] - mnew);
            float ls = (p0 + p1) + (p2 + p3);
            ls += __shfl_xor_sync(0xffffffffu, ls, 1);
            ls += __shfl_xor_sync(0xffffffffu, ls, 2);
            ls += __shfl_xor_sync(0xffffffffu, ls, 4);
            ls += __shfl_xor_sync(0xffffffffu, ls, 8);
            l[i] = l[i]*corr + ls;
            m[i] = mnew;
            *(float4*)(Ps + (ry*4 + i)*68 + tx*4) = make_float4(p0, p1, p2, p3);
            #pragma unroll
            for (int jp = 0; jp < 4; jp++) { o[i][jp].x *= corr; o[i][jp].y *= corr; }
        }
        __syncthreads();

        // O += P @ V  (64x128x64)
        #pragma unroll 4
        for (int kk = 0; kk < 64; kk++) {
            float a[4];
            #pragma unroll
            for (int i = 0; i < 4; i++) a[i] = Ps[(ry*4 + i)*68 + kk];
            float4 b0 = *(float4*)(Vs + kk*128 + tx*8);
            float4 b1 = *(float4*)(Vs + kk*128 + tx*8 + 4);
            #pragma unroll
            for (int i = 0; i < 4; i++) {
                ffma2(o[i][0], a[i], make_float2(b0.x, b0.y));
                ffma2(o[i][1], a[i], make_float2(b0.z, b0.w));
                ffma2(o[i][2], a[i], make_float2(b1.x, b1.y));
                ffma2(o[i][3], a[i], make_float2(b1.z, b1.w));
            }
        }
        __syncthreads();
    }

    // Epilogue: normalize and write.
    #pragma unroll
    for (int i = 0; i < 4; i++) {
        float inv = 1.0f / l[i];
        int row = qi*64 + ry*4 + i;
        float* op = out + (b*T_ + row)*H_ + tx*8;
        *(float4*)(op)     = make_float4(o[i][0].x*inv, o[i][0].y*inv,
                                         o[i][1].x*inv, o[i][1].y*inv);
        *(float4*)(op + 4) = make_float4(o[i][2].x*inv, o[i][2].y*inv,
                                         o[i][3].x*inv, o[i][3].y*inv);
    }
}

extern "C" void kernel_launch(void* const* d_in, const int* in_sizes, int n_in,
                              void* d_out, int out_size)
{
    const float* x  = (const float*)d_in[0];
    const float* Wq = (const float*)d_in[1];
    const float* Wk = (const float*)d_in[2];
    const float* Wv = (const float*)d_in[3];
    float* out = (float*)d_out;

    proj_kernel<<<dim3(BT_/64, 3), 256>>>(x, Wq, Wk, Wv);

    const int smem = (64*132 + 128*64 + 64*128 + 64*68) * (int)sizeof(float); // 116736 B
    cudaFuncSetAttribute(attn_kernel, cudaFuncAttributeMaxDynamicSharedMemorySize, smem);
    attn_kernel<<<dim3(T_/64, B_), 256, smem>>>(out);
}

// round 2
// speedup vs baseline: 2.4750x; 2.4750x over previous
#include <cuda_runtime.h>
#include <cuda_bf16.h>
#include <stdint.h>

#define B_  8
#define T_  2048
#define E_  1024
#define H_  128
#define BT_ (B_*T_)

// ---- global scratch (alloc-free rules: __device__ globals) ----
__device__ __nv_bfloat16 gx_h[BT_*E_];
__device__ __nv_bfloat16 gx_l[BT_*E_];
__device__ __nv_bfloat16 gw_h[3][E_*H_];
__device__ __nv_bfloat16 gw_l[3][E_*H_];
__device__ __nv_bfloat16 gq_h[BT_*H_];
__device__ __nv_bfloat16 gq_l[BT_*H_];
__device__ __nv_bfloat16 gk_h[BT_*H_];
__device__ __nv_bfloat16 gk_l[BT_*H_];
__device__ __nv_bfloat16 gv_h[BT_*H_];
__device__ __nv_bfloat16 gv_l[BT_*H_];

// ---- helpers ----
__device__ __forceinline__ void ldm_x4(uint32_t* r, const void* p) {
    uint32_t a = (uint32_t)__cvta_generic_to_shared(p);
    asm volatile("ldmatrix.sync.aligned.m8n8.x4.shared.b16 {%0,%1,%2,%3}, [%4];"
                 : "=r"(r[0]), "=r"(r[1]), "=r"(r[2]), "=r"(r[3]) : "r"(a));
}
__device__ __forceinline__ void ldm_x4_t(uint32_t* r, const void* p) {
    uint32_t a = (uint32_t)__cvta_generic_to_shared(p);
    asm volatile("ldmatrix.sync.aligned.m8n8.x4.trans.shared.b16 {%0,%1,%2,%3}, [%4];"
                 : "=r"(r[0]), "=r"(r[1]), "=r"(r[2]), "=r"(r[3]) : "r"(a));
}
__device__ __forceinline__ void mma16816(float* d, const uint32_t* a, const uint32_t* b) {
    asm volatile("mma.sync.aligned.m16n8k16.row.col.f32.bf16.bf16.f32 "
                 "{%0,%1,%2,%3}, {%4,%5,%6,%7}, {%8,%9}, {%0,%1,%2,%3};"
                 : "+f"(d[0]), "+f"(d[1]), "+f"(d[2]), "+f"(d[3])
                 : "r"(a[0]), "r"(a[1]), "r"(a[2]), "r"(a[3]), "r"(b[0]), "r"(b[1]));
}
__device__ __forceinline__ uint32_t pack_hi2(float a, float b) {
    __nv_bfloat162 h;
    h.x = __float2bfloat16_rn(a);
    h.y = __float2bfloat16_rn(b);
    return *reinterpret_cast<uint32_t*>(&h);
}
__device__ __forceinline__ uint32_t pack_lo2(float a, float b) {
    __nv_bfloat16 ha = __float2bfloat16_rn(a);
    __nv_bfloat16 hb = __float2bfloat16_rn(b);
    __nv_bfloat162 l;
    l.x = __float2bfloat16_rn(a - __bfloat162float(ha));
    l.y = __float2bfloat16_rn(b - __bfloat162float(hb));
    return *reinterpret_cast<uint32_t*>(&l);
}

// ---------------------------------------------------------------------------
// Split x into bf16 hi/lo. 1 float4 per thread.
// ---------------------------------------------------------------------------
__global__ void split_x_kernel(const float* __restrict__ x)
{
    int i = blockIdx.x * 256 + threadIdx.x;
    float4 v = reinterpret_cast<const float4*>(x)[i];
    float f[4] = {v.x, v.y, v.z, v.w};
    uint2 hv, lv;
    hv.x = pack_hi2(f[0], f[1]); hv.y = pack_hi2(f[2], f[3]);
    lv.x = pack_lo2(f[0], f[1]); lv.y = pack_lo2(f[2], f[3]);
    reinterpret_cast<uint2*>(gx_h)[i] = hv;
    reinterpret_cast<uint2*>(gx_l)[i] = lv;
}

__global__ void split_w_kernel(const float* __restrict__ Wq,
                               const float* __restrict__ Wk,
                               const float* __restrict__ Wv)
{
    const float* W = (blockIdx.y == 0) ? Wq : (blockIdx.y == 1) ? Wk : Wv;
    __nv_bfloat16* oh = gw_h[blockIdx.y];
    __nv_bfloat16* ol = gw_l[blockIdx.y];
    int i = blockIdx.x * 256 + threadIdx.x;
    float4 v = reinterpret_cast<const float4*>(W)[i];
    float f[4] = {v.x, v.y, v.z, v.w};
    uint2 hv, lv;
    hv.x = pack_hi2(f[0], f[1]); hv.y = pack_hi2(f[2], f[3]);
    lv.x = pack_lo2(f[0], f[1]); lv.y = pack_lo2(f[2], f[3]);
    reinterpret_cast<uint2*>(oh)[i] = hv;
    reinterpret_cast<uint2*>(ol)[i] = lv;
}

// ---------------------------------------------------------------------------
// Projection via mma.sync bf16x3: out = x @ W. CTA: 64 rows x 128 cols,
// 4 warps, each warp = 16 rows x 128 cols = 1 m-frag x 16 n-frags.
// Writes hi/lo splits of q (pre-scaled by 1/sqrt(H)), k, v.
// smem per tile: X [64][72] hi/lo, W [64][136] hi/lo (padded, conflict-free).
// ---------------------------------------------------------------------------
__global__ __launch_bounds__(128) void proj_mma(
    const float* dummy /* unused, keeps signature nonempty */)
{
    extern __shared__ __nv_bfloat16 smp[];
    __nv_bfloat16* Xh = smp;
    __nv_bfloat16* Xl = Xh + 64*72;
    __nv_bfloat16* Wh = Xl + 64*72;
    __nv_bfloat16* Wl = Wh + 64*136;

    const int mat = blockIdx.y;
    const __nv_bfloat16* wh = gw_h[mat];
    const __nv_bfloat16* wl = gw_l[mat];
    __nv_bfloat16 *oh, *ol;
    if (mat == 0)      { oh = gq_h; ol = gq_l; }
    else if (mat == 1) { oh = gk_h; ol = gk_l; }
    else               { oh = gv_h; ol = gv_l; }

    const int r0   = blockIdx.x * 64;
    const int tid  = threadIdx.x;
    const int wrp  = tid >> 5;
    const int lane = tid & 31;
    const int g    = lane >> 2;
    const int tg   = lane & 3;

    float acc[16][4];
    #pragma unroll
    for (int f = 0; f < 16; f++)
        #pragma unroll
        for (int e = 0; e < 4; e++) acc[f][e] = 0.f;

    for (int kc = 0; kc < 16; kc++) {
        const int k0 = kc * 64;
        __syncthreads();
        // X tiles: 512 uint4 per split
        #pragma unroll
        for (int it = 0; it < 4; it++) {
            int idx = it*128 + tid;
            int row = idx >> 3, u = idx & 7;
            size_t src = (size_t)(r0 + row) * E_ + k0 + u*8;
            *reinterpret_cast<uint4*>(Xh + row*72 + u*8) = *reinterpret_cast<const uint4*>(gx_h + src);
            *reinterpret_cast<uint4*>(Xl + row*72 + u*8) = *reinterpret_cast<const uint4*>(gx_l + src);
        }
        // W tiles: 1024 uint4 per split
        #pragma unroll
        for (int it = 0; it < 8; it++) {
            int idx = it*128 + tid;
            int row = idx >> 4, u = idx & 15;
            size_t src = (size_t)(k0 + row) * H_ + u*8;
            *reinterpret_cast<uint4*>(Wh + row*136 + u*8) = *reinterpret_cast<const uint4*>(wh + src);
            *reinterpret_cast<uint4*>(Wl + row*136 + u*8) = *reinterpret_cast<const uint4*>(wl + src);
        }
        __syncthreads();

        #pragma unroll
        for (int kk = 0; kk < 4; kk++) {
            uint32_t ah[4], al[4];
            const int arow = 16*wrp + (lane & 15);
            const int acol = kk*16 + (lane >> 4) * 8;
            ldm_x4(ah, Xh + arow*72 + acol);
            ldm_x4(al, Xl + arow*72 + acol);
            #pragma unroll
            for (int fp = 0; fp < 8; fp++) {
                uint32_t bh[4], bl[4];
                const int brow = kk*16 + (lane & 7) + ((lane >> 3) & 1) * 8;
                const int bcol = fp*16 + ((lane >> 4) & 1) * 8;
                ldm_x4_t(bh, Wh + brow*136 + bcol);
                ldm_x4_t(bl, Wl + brow*136 + bcol);
                mma16816(acc[2*fp],   ah, &bh[0]);
                mma16816(acc[2*fp],   ah, &bl[0]);
                mma16816(acc[2*fp],   al, &bh[0]);
                mma16816(acc[2*fp+1], ah, &bh[2]);
                mma16816(acc[2*fp+1], ah, &bl[2]);
                mma16816(acc[2*fp+1], al, &bh[2]);
            }
        }
    }

    // Epilogue: (optionally scale q by 1/sqrt(H)), split to bf16 hi/lo, store.
    const float scale = (mat == 0) ? 0.08838834764831845f : 1.0f;
    const int row0 = r0 + wrp*16 + g;
    const int row1 = row0 + 8;
    #pragma unroll
    for (int f = 0; f < 16; f++) {
        const int col = f*8 + tg*2;
        float v0 = acc[f][0]*scale, v1 = acc[f][1]*scale;
        float v2 = acc[f][2]*scale, v3 = acc[f][3]*scale;
        *reinterpret_cast<uint32_t*>(oh + (size_t)row0*H_ + col) = pack_hi2(v0, v1);
        *reinterpret_cast<uint32_t*>(ol + (size_t)row0*H_ + col) = pack_lo2(v0, v1);
        *reinterpret_cast<uint32_t*>(oh + (size_t)row1*H_ + col) = pack_hi2(v2, v3);
        *reinterpret_cast<uint32_t*>(ol + (size_t)row1*H_ + col) = pack_lo2(v2, v3);
    }
}

// ---------------------------------------------------------------------------
// Flash attention via mma.sync bf16x3. CTA: 64 q-rows, KV tiles of 64.
// 4 warps; warp owns 16 q-rows. S D-frags map directly onto PV A-frags.
// Q is pre-scaled by 1/sqrt(H) in proj.
// ---------------------------------------------------------------------------
__global__ __launch_bounds__(128, 2) void attn_mma(float* __restrict__ out)
{
    extern __shared__ __nv_bfloat16 sma[];
    __nv_bfloat16* Qh = sma;
    __nv_bfloat16* Ql = Qh + 64*136;
    __nv_bfloat16* Kh = Ql + 64*136;
    __nv_bfloat16* Kl = Kh + 64*136;
    __nv_bfloat16* Vh = Kl + 64*136;
    __nv_bfloat16* Vl = Vh + 64*136;

    const int b    = blockIdx.y;
    const int qi   = (int)gridDim.x - 1 - (int)blockIdx.x;  // longest first
    const int q0   = qi * 64;
    const int tid  = threadIdx.x;
    const int wrp  = tid >> 5;
    const int lane = tid & 31;
    const int g    = lane >> 2;
    const int tg   = lane & 3;

    // Load Q tile hi/lo (1024 uint4 per split)
    {
        const __nv_bfloat16* qh = gq_h + (size_t)(b*T_ + q0) * H_;
        const __nv_bfloat16* ql = gq_l + (size_t)(b*T_ + q0) * H_;
        #pragma unroll
        for (int it = 0; it < 8; it++) {
            int idx = it*128 + tid;
            int row = idx >> 4, u = idx & 15;
            *reinterpret_cast<uint4*>(Qh + row*136 + u*8) = *reinterpret_cast<const uint4*>(qh + row*H_ + u*8);
            *reinterpret_cast<uint4*>(Ql + row*136 + u*8) = *reinterpret_cast<const uint4*>(ql + row*H_ + u*8);
        }
    }

    float o[16][4];
    #pragma unroll
    for (int f = 0; f < 16; f++)
        #pragma unroll
        for (int e = 0; e < 4; e++) o[f][e] = 0.f;
    float m0 = -1e30f, m1 = -1e30f, l0 = 0.f, l1 = 0.f;

    for (int j = 0; j <= qi; j++) {
        __syncthreads();   // prev compute done (and Q visible on first iter)
        {
            const __nv_bfloat16* kh = gk_h + (size_t)(b*T_ + j*64) * H_;
            const __nv_bfloat16* kl = gk_l + (size_t)(b*T_ + j*64) * H_;
            const __nv_bfloat16* vh = gv_h + (size_t)(b*T_ + j*64) * H_;
            const __nv_bfloat16* vl = gv_l + (size_t)(b*T_ + j*64) * H_;
            #pragma unroll
            for (int it = 0; it < 8; it++) {
                int idx = it*128 + tid;
                int row = idx >> 4, u = idx & 15;
                *reinterpret_cast<uint4*>(Kh + row*136 + u*8) = *reinterpret_cast<const uint4*>(kh + row*H_ + u*8);
                *reinterpret_cast<uint4*>(Kl + row*136 + u*8) = *reinterpret_cast<const uint4*>(kl + row*H_ + u*8);
                *reinterpret_cast<uint4*>(Vh + row*136 + u*8) = *reinterpret_cast<const uint4*>(vh + row*H_ + u*8);
                *reinterpret_cast<uint4*>(Vl + row*136 + u*8) = *reinterpret_cast<const uint4*>(vl + row*H_ + u*8);
            }
        }
        __syncthreads();

        // ---- S = Q @ K^T (logits already scaled) ----
        float s[8][4];
        #pragma unroll
        for (int f = 0; f < 8; f++)
            #pragma unroll
            for (int e = 0; e < 4; e++) s[f][e] = 0.f;

        #pragma unroll
        for (int kk = 0; kk < 8; kk++) {
            uint32_t ah[4], al[4];
            const int arow = 16*wrp + (lane & 15);
            const int acol = kk*16 + (lane >> 4) * 8;
            ldm_x4(ah, Qh + arow*136 + acol);
            ldm_x4(al, Ql + arow*136 + acol);
            #pragma unroll
            for (int fp = 0; fp < 4; fp++) {
                uint32_t bh[4], bl[4];
                const int brow = fp*16 + (lane & 7) + ((lane >> 4) & 1) * 8;  // kv row
                const int bcol = kk*16 + ((lane >> 3) & 1) * 8;               // h col
                ldm_x4(bh, Kh + brow*136 + bcol);
                ldm_x4(bl, Kl + brow*136 + bcol);
                mma16816(s[2*fp],   ah, &bh[0]);
                mma16816(s[2*fp],   ah, &bl[0]);
                mma16816(s[2*fp],   al, &bh[0]);
                mma16816(s[2*fp+1], ah, &bh[2]);
                mma16816(s[2*fp+1], ah, &bl[2]);
                mma16816(s[2*fp+1], al, &bh[2]);
            }
        }

        // ---- causal mask on diagonal tile ----
        if (j == qi) {
            #pragma unroll
            for (int f = 0; f < 8; f++) {
                #pragma unroll
                for (int e = 0; e < 4; e++) {
                    int col = f*8 + tg*2 + (e & 1);
                    int row = wrp*16 + g + ((e >> 1) ? 8 : 0);
                    if (col > row) s[f][e] = -1e30f;
                }
            }
        }

        // ---- online softmax (rows g / g+8; reduce across 4 tg lanes) ----
        float rm0 = -1e30f, rm1 = -1e30f;
        #pragma unroll
        for (int f = 0; f < 8; f++) {
            rm0 = fmaxf(rm0, fmaxf(s[f][0], s[f][1]));
            rm1 = fmaxf(rm1, fmaxf(s[f][2], s[f][3]));
        }
        rm0 = fmaxf(rm0, __shfl_xor_sync(0xffffffffu, rm0, 1));
        rm0 = fmaxf(rm0, __shfl_xor_sync(0xffffffffu, rm0, 2));
        rm1 = fmaxf(rm1, __shfl_xor_sync(0xffffffffu, rm1, 1));
        rm1 = fmaxf(rm1, __shfl_xor_sync(0xffffffffu, rm1, 2));
        const float mn0 = fmaxf(m0, rm0), mn1 = fmaxf(m1, rm1);
        const float c0 = __expf(m0 - mn0), c1 = __expf(m1 - mn1);
        float ls0 = 0.f, ls1 = 0.f;
        #pragma unroll
        for (int f = 0; f < 8; f++) {
            s[f][0] = __expf(s[f][0] - mn0);
            s[f][1] = __expf(s[f][1] - mn0);
            s[f][2] = __expf(s[f][2] - mn1);
            s[f][3] = __expf(s[f][3] - mn1);
            ls0 += s[f][0] + s[f][1];
            ls1 += s[f][2] + s[f][3];
        }
        ls0 += __shfl_xor_sync(0xffffffffu, ls0, 1);
        ls0 += __shfl_xor_sync(0xffffffffu, ls0, 2);
        ls1 += __shfl_xor_sync(0xffffffffu, ls1, 1);
        ls1 += __shfl_xor_sync(0xffffffffu, ls1, 2);
        l0 = l0*c0 + ls0; l1 = l1*c1 + ls1;
        m0 = mn0; m1 = mn1;
        #pragma unroll
        for (int f = 0; f < 16; f++) {
            o[f][0] *= c0; o[f][1] *= c0;
            o[f][2] *= c1; o[f][3] *= c1;
        }

        // ---- O += P @ V ----
        #pragma unroll
        for (int kk = 0; kk < 4; kk++) {
            uint32_t ah[4], al[4];
            ah[0] = pack_hi2(s[2*kk][0],   s[2*kk][1]);
            ah[1] = pack_hi2(s[2*kk][2],   s[2*kk][3]);
            ah[2] = pack_hi2(s[2*kk+1][0], s[2*kk+1][1]);
            ah[3] = pack_hi2(s[2*kk+1][2], s[2*kk+1][3]);
            al[0] = pack_lo2(s[2*kk][0],   s[2*kk][1]);
            al[1] = pack_lo2(s[2*kk][2],   s[2*kk][3]);
            al[2] = pack_lo2(s[2*kk+1][0], s[2*kk+1][1]);
            al[3] = pack_lo2(s[2*kk+1][2], s[2*kk+1][3]);
            #pragma unroll
            for (int fp = 0; fp < 8; fp++) {
                uint32_t bh[4], bl[4];
                const int brow = kk*16 + (lane & 7) + ((lane >> 3) & 1) * 8;  // kv row
                const int bcol = fp*16 + ((lane >> 4) & 1) * 8;               // h col
                ldm_x4_t(bh, Vh + brow*136 + bcol);
                ldm_x4_t(bl, Vl + brow*136 + bcol);
                mma16816(o[2*fp],   ah, &bh[0]);
                mma16816(o[2*fp],   ah, &bl[0]);
                mma16816(o[2*fp],   al, &bh[0]);
                mma16816(o[2*fp+1], ah, &bh[2]);
                mma16816(o[2*fp+1], ah, &bl[2]);
                mma16816(o[2*fp+1], al, &bh[2]);
            }
        }
    }

    // ---- epilogue ----
    const float inv0 = 1.0f / l0, inv1 = 1.0f / l1;
    const size_t row0 = (size_t)b*T_ + q0 + wrp*16 + g;
    const size_t row1 = row0 + 8;
    #pragma unroll
    for (int f = 0; f < 16; f++) {
        const int col = f*8 + tg*2;
        float2 v0 = make_float2(o[f][0]*inv0, o[f][1]*inv0);
        float2 v1 = make_float2(o[f][2]*inv1, o[f][3]*inv1);
        *reinterpret_cast<float2*>(out + row0*H_ + col) = v0;
        *reinterpret_cast<float2*>(out + row1*H_ + col) = v1;
    }
}

extern "C" void kernel_launch(void* const* d_in, const int* in_sizes, int n_in,
                              void* d_out, int out_size)
{
    const float* x  = (const float*)d_in[0];
    const float* Wq = (const float*)d_in[1];
    const float* Wk = (const float*)d_in[2];
    const float* Wv = (const float*)d_in[3];
    float* out = (float*)d_out;

    const int proj_smem = (2*64*72 + 2*64*136) * (int)sizeof(__nv_bfloat16);  // 53248
    const int attn_smem = 6*64*136 * (int)sizeof(__nv_bfloat16);              // 104448
    cudaFuncSetAttribute(proj_mma, cudaFuncAttributeMaxDynamicSharedMemorySize, proj_smem);
    cudaFuncSetAttribute(attn_mma, cudaFuncAttributeMaxDynamicSharedMemorySize, attn_smem);

    split_x_kernel<<<BT_*E_/4/256, 256>>>(x);
    split_w_kernel<<<dim3(E_*H_/4/256, 3), 256>>>(Wq, Wk, Wv);
    proj_mma<<<dim3(BT_/64, 3), 128, proj_smem>>>(x);
    attn_mma<<<dim3(T_/64, B_), 128, attn_smem>>>(out);
}

// round 3
// speedup vs baseline: 2.8114x; 1.1359x over previous
#include <cuda_runtime.h>
#include <cuda_bf16.h>
#include <stdint.h>

#define B_  8
#define T_  2048
#define E_  1024
#define H_  128
#define BT_ (B_*T_)

// ---- global scratch ----
__device__ __nv_bfloat16 gx_h[BT_*E_];
__device__ __nv_bfloat16 gx_l[BT_*E_];
__device__ __nv_bfloat16 gw_h[3][E_*H_];
__device__ __nv_bfloat16 gw_l[3][E_*H_];
__device__ __nv_bfloat16 gq_h[BT_*H_];
__device__ __nv_bfloat16 gq_l[BT_*H_];
__device__ __nv_bfloat16 gk_h[BT_*H_];
__device__ __nv_bfloat16 gk_l[BT_*H_];
__device__ __nv_bfloat16 gv_h[BT_*H_];
__device__ __nv_bfloat16 gv_l[BT_*H_];

// ---- helpers ----
__device__ __forceinline__ void ldm_x4(uint32_t* r, const void* p) {
    uint32_t a = (uint32_t)__cvta_generic_to_shared(p);
    asm volatile("ldmatrix.sync.aligned.m8n8.x4.shared.b16 {%0,%1,%2,%3}, [%4];"
                 : "=r"(r[0]), "=r"(r[1]), "=r"(r[2]), "=r"(r[3]) : "r"(a));
}
__device__ __forceinline__ void ldm_x4_t(uint32_t* r, const void* p) {
    uint32_t a = (uint32_t)__cvta_generic_to_shared(p);
    asm volatile("ldmatrix.sync.aligned.m8n8.x4.trans.shared.b16 {%0,%1,%2,%3}, [%4];"
                 : "=r"(r[0]), "=r"(r[1]), "=r"(r[2]), "=r"(r[3]) : "r"(a));
}
__device__ __forceinline__ void mma16816(float* d, const uint32_t* a, const uint32_t* b) {
    asm volatile("mma.sync.aligned.m16n8k16.row.col.f32.bf16.bf16.f32 "
                 "{%0,%1,%2,%3}, {%4,%5,%6,%7}, {%8,%9}, {%0,%1,%2,%3};"
                 : "+f"(d[0]), "+f"(d[1]), "+f"(d[2]), "+f"(d[3])
                 : "r"(a[0]), "r"(a[1]), "r"(a[2]), "r"(a[3]), "r"(b[0]), "r"(b[1]));
}
__device__ __forceinline__ uint32_t pack_hi2(float a, float b) {
    __nv_bfloat162 h;
    h.x = __float2bfloat16_rn(a);
    h.y = __float2bfloat16_rn(b);
    return *reinterpret_cast<uint32_t*>(&h);
}
__device__ __forceinline__ uint32_t pack_lo2(float a, float b) {
    __nv_bfloat16 ha = __float2bfloat16_rn(a);
    __nv_bfloat16 hb = __float2bfloat16_rn(b);
    __nv_bfloat162 l;
    l.x = __float2bfloat16_rn(a - __bfloat162float(ha));
    l.y = __float2bfloat16_rn(b - __bfloat162float(hb));
    return *reinterpret_cast<uint32_t*>(&l);
}
__device__ __forceinline__ void cp16(void* smem, const void* gmem) {
    uint32_t a = (uint32_t)__cvta_generic_to_shared(smem);
    asm volatile("cp.async.cg.shared.global [%0], [%1], 16;" :: "r"(a), "l"(gmem));
}
__device__ __forceinline__ void cp_commit() {
    asm volatile("cp.async.commit_group;");
}
template<int N>
__device__ __forceinline__ void cp_wait() {
    asm volatile("cp.async.wait_group %0;" :: "n"(N));
}

// ---------------------------------------------------------------------------
// Split kernels
// ---------------------------------------------------------------------------
__global__ void split_x_kernel(const float* __restrict__ x)
{
    int i = blockIdx.x * 256 + threadIdx.x;
    float4 v = reinterpret_cast<const float4*>(x)[i];
    uint2 hv, lv;
    hv.x = pack_hi2(v.x, v.y); hv.y = pack_hi2(v.z, v.w);
    lv.x = pack_lo2(v.x, v.y); lv.y = pack_lo2(v.z, v.w);
    reinterpret_cast<uint2*>(gx_h)[i] = hv;
    reinterpret_cast<uint2*>(gx_l)[i] = lv;
}

__global__ void split_w_kernel(const float* __restrict__ Wq,
                               const float* __restrict__ Wk,
                               const float* __restrict__ Wv)
{
    const float* W = (blockIdx.y == 0) ? Wq : (blockIdx.y == 1) ? Wk : Wv;
    __nv_bfloat16* oh = gw_h[blockIdx.y];
    __nv_bfloat16* ol = gw_l[blockIdx.y];
    int i = blockIdx.x * 256 + threadIdx.x;
    float4 v = reinterpret_cast<const float4*>(W)[i];
    uint2 hv, lv;
    hv.x = pack_hi2(v.x, v.y); hv.y = pack_hi2(v.z, v.w);
    lv.x = pack_lo2(v.x, v.y); lv.y = pack_lo2(v.z, v.w);
    reinterpret_cast<uint2*>(oh)[i] = hv;
    reinterpret_cast<uint2*>(ol)[i] = lv;
}

// ---------------------------------------------------------------------------
// Projection, 2-stage cp.async pipeline.
// Stage = Xh/Xl [64][72] + Wh/Wl [64][136].
// ---------------------------------------------------------------------------
#define PX_ (64*72)
#define PW_ (64*136)

__global__ __launch_bounds__(128) void proj_mma()
{
    extern __shared__ __nv_bfloat16 smp[];
    __nv_bfloat16* Xh = smp;               // [2][64*72]
    __nv_bfloat16* Xl = Xh + 2*PX_;
    __nv_bfloat16* Wh = Xl + 2*PX_;        // [2][64*136]
    __nv_bfloat16* Wl = Wh + 2*PW_;

    const int mat = blockIdx.y;
    const __nv_bfloat16* wh = gw_h[mat];
    const __nv_bfloat16* wl = gw_l[mat];
    __nv_bfloat16 *oh, *ol;
    if (mat == 0)      { oh = gq_h; ol = gq_l; }
    else if (mat == 1) { oh = gk_h; ol = gk_l; }
    else               { oh = gv_h; ol = gv_l; }

    const int r0   = blockIdx.x * 64;
    const int tid  = threadIdx.x;
    const int wrp  = tid >> 5;
    const int lane = tid & 31;
    const int g    = lane >> 2;
    const int tg   = lane & 3;

    // load issue for k-chunk kc into stage s
    auto issue = [&](int kc, int s) {
        const int k0 = kc * 64;
        #pragma unroll
        for (int it = 0; it < 4; it++) {
            int idx = it*128 + tid;
            int row = idx >> 3, u = idx & 7;
            size_t src = (size_t)(r0 + row) * E_ + k0 + u*8;
            cp16(Xh + s*PX_ + row*72 + u*8, gx_h + src);
            cp16(Xl + s*PX_ + row*72 + u*8, gx_l + src);
        }
        #pragma unroll
        for (int it = 0; it < 8; it++) {
            int idx = it*128 + tid;
            int row = idx >> 4, u = idx & 15;
            size_t src = (size_t)(k0 + row) * H_ + u*8;
            cp16(Wh + s*PW_ + row*136 + u*8, wh + src);
            cp16(Wl + s*PW_ + row*136 + u*8, wl + src);
        }
        cp_commit();
    };

    float acc[16][4];
    #pragma unroll
    for (int f = 0; f < 16; f++)
        #pragma unroll
        for (int e = 0; e < 4; e++) acc[f][e] = 0.f;

    issue(0, 0);

    for (int kc = 0; kc < 16; kc++) {
        const int s = kc & 1;
        if (kc < 15) { issue(kc+1, s^1); cp_wait<1>(); }
        else         { cp_wait<0>(); }
        __syncthreads();

        const __nv_bfloat16* xh = Xh + s*PX_;
        const __nv_bfloat16* xl = Xl + s*PX_;
        const __nv_bfloat16* whs = Wh + s*PW_;
        const __nv_bfloat16* wls = Wl + s*PW_;

        #pragma unroll
        for (int kk = 0; kk < 4; kk++) {
            uint32_t ah[4], al[4];
            const int arow = 16*wrp + (lane & 15);
            const int acol = kk*16 + (lane >> 4) * 8;
            ldm_x4(ah, xh + arow*72 + acol);
            ldm_x4(al, xl + arow*72 + acol);
            #pragma unroll
            for (int fp = 0; fp < 8; fp++) {
                uint32_t bh[4], bl[4];
                const int brow = kk*16 + (lane & 7) + ((lane >> 3) & 1) * 8;
                const int bcol = fp*16 + ((lane >> 4) & 1) * 8;
                ldm_x4_t(bh, whs + brow*136 + bcol);
                ldm_x4_t(bl, wls + brow*136 + bcol);
                mma16816(acc[2*fp],   ah, &bh[0]);
                mma16816(acc[2*fp],   ah, &bl[0]);
                mma16816(acc[2*fp],   al, &bh[0]);
                mma16816(acc[2*fp+1], ah, &bh[2]);
                mma16816(acc[2*fp+1], ah, &bl[2]);
                mma16816(acc[2*fp+1], al, &bh[2]);
            }
        }
        __syncthreads();
    }

    const float scale = (mat == 0) ? 0.08838834764831845f : 1.0f;
    const int row0 = r0 + wrp*16 + g;
    const int row1 = row0 + 8;
    #pragma unroll
    for (int f = 0; f < 16; f++) {
        const int col = f*8 + tg*2;
        float v0 = acc[f][0]*scale, v1 = acc[f][1]*scale;
        float v2 = acc[f][2]*scale, v3 = acc[f][3]*scale;
        *reinterpret_cast<uint32_t*>(oh + (size_t)row0*H_ + col) = pack_hi2(v0, v1);
        *reinterpret_cast<uint32_t*>(ol + (size_t)row0*H_ + col) = pack_lo2(v0, v1);
        *reinterpret_cast<uint32_t*>(oh + (size_t)row1*H_ + col) = pack_hi2(v2, v3);
        *reinterpret_cast<uint32_t*>(ol + (size_t)row1*H_ + col) = pack_lo2(v2, v3);
    }
}

// ---------------------------------------------------------------------------
// Flash attention, 2-stage cp.async KV pipeline. 4 warps, 64 q-rows, KV64.
// ---------------------------------------------------------------------------
#define AT_ (64*136)

__global__ __launch_bounds__(128, 1) void attn_mma(float* __restrict__ out)
{
    extern __shared__ __nv_bfloat16 sma[];
    __nv_bfloat16* Qh = sma;               // [64*136]
    __nv_bfloat16* Ql = Qh + AT_;
    __nv_bfloat16* Kh = Ql + AT_;          // [2][64*136]
    __nv_bfloat16* Kl = Kh + 2*AT_;
    __nv_bfloat16* Vh = Kl + 2*AT_;
    __nv_bfloat16* Vl = Vh + 2*AT_;

    const int b    = blockIdx.y;
    const int qi   = (int)gridDim.x - 1 - (int)blockIdx.x;  // longest first
    const int q0   = qi * 64;
    const int tid  = threadIdx.x;
    const int wrp  = tid >> 5;
    const int lane = tid & 31;
    const int g    = lane >> 2;
    const int tg   = lane & 3;

    auto issue_kv = [&](int j, int s) {
        const __nv_bfloat16* kh = gk_h + (size_t)(b*T_ + j*64) * H_;
        const __nv_bfloat16* kl = gk_l + (size_t)(b*T_ + j*64) * H_;
        const __nv_bfloat16* vh = gv_h + (size_t)(b*T_ + j*64) * H_;
        const __nv_bfloat16* vl = gv_l + (size_t)(b*T_ + j*64) * H_;
        #pragma unroll
        for (int it = 0; it < 8; it++) {
            int idx = it*128 + tid;
            int row = idx >> 4, u = idx & 15;
            int d = row*136 + u*8;
            size_t src = (size_t)row*H_ + u*8;
            cp16(Kh + s*AT_ + d, kh + src);
            cp16(Kl + s*AT_ + d, kl + src);
            cp16(Vh + s*AT_ + d, vh + src);
            cp16(Vl + s*AT_ + d, vl + src);
        }
        cp_commit();
    };

    // prologue: Q + stage 0 (one group)
    {
        const __nv_bfloat16* qh = gq_h + (size_t)(b*T_ + q0) * H_;
        const __nv_bfloat16* ql = gq_l + (size_t)(b*T_ + q0) * H_;
        #pragma unroll
        for (int it = 0; it < 8; it++) {
            int idx = it*128 + tid;
            int row = idx >> 4, u = idx & 15;
            int d = row*136 + u*8;
            size_t src = (size_t)row*H_ + u*8;
            cp16(Qh + d, qh + src);
            cp16(Ql + d, ql + src);
        }
        const __nv_bfloat16* kh = gk_h + (size_t)(b*T_) * H_;
        const __nv_bfloat16* kl = gk_l + (size_t)(b*T_) * H_;
        const __nv_bfloat16* vh = gv_h + (size_t)(b*T_) * H_;
        const __nv_bfloat16* vl = gv_l + (size_t)(b*T_) * H_;
        #pragma unroll
        for (int it = 0; it < 8; it++) {
            int idx = it*128 + tid;
            int row = idx >> 4, u = idx & 15;
            int d = row*136 + u*8;
            size_t src = (size_t)row*H_ + u*8;
            cp16(Kh + d, kh + src);
            cp16(Kl + d, kl + src);
            cp16(Vh + d, vh + src);
            cp16(Vl + d, vl + src);
        }
        cp_commit();
    }

    float o[16][4];
    #pragma unroll
    for (int f = 0; f < 16; f++)
        #pragma unroll
        for (int e = 0; e < 4; e++) o[f][e] = 0.f;
    float m0 = -1e30f, m1 = -1e30f, l0 = 0.f, l1 = 0.f;

    for (int j = 0; j <= qi; j++) {
        const int s = j & 1;
        if (j < qi) { issue_kv(j+1, s^1); cp_wait<1>(); }
        else        { cp_wait<0>(); }
        __syncthreads();

        const __nv_bfloat16* kh = Kh + s*AT_;
        const __nv_bfloat16* kl = Kl + s*AT_;
        const __nv_bfloat16* vh = Vh + s*AT_;
        const __nv_bfloat16* vl = Vl + s*AT_;

        // ---- S = Q @ K^T ----
        float sv[8][4];
        #pragma unroll
        for (int f = 0; f < 8; f++)
            #pragma unroll
            for (int e = 0; e < 4; e++) sv[f][e] = 0.f;

        #pragma unroll
        for (int kk = 0; kk < 8; kk++) {
            uint32_t ah[4], al[4];
            const int arow = 16*wrp + (lane & 15);
            const int acol = kk*16 + (lane >> 4) * 8;
            ldm_x4(ah, Qh + arow*136 + acol);
            ldm_x4(al, Ql + arow*136 + acol);
            #pragma unroll
            for (int fp = 0; fp < 4; fp++) {
                uint32_t bh[4], bl[4];
                const int brow = fp*16 + (lane & 7) + ((lane >> 4) & 1) * 8;
                const int bcol = kk*16 + ((lane >> 3) & 1) * 8;
                ldm_x4(bh, kh + brow*136 + bcol);
                ldm_x4(bl, kl + brow*136 + bcol);
                mma16816(sv[2*fp],   ah, &bh[0]);
                mma16816(sv[2*fp],   ah, &bl[0]);
                mma16816(sv[2*fp],   al, &bh[0]);
                mma16816(sv[2*fp+1], ah, &bh[2]);
                mma16816(sv[2*fp+1], ah, &bl[2]);
                mma16816(sv[2*fp+1], al, &bh[2]);
            }
        }

        // ---- causal mask ----
        if (j == qi) {
            #pragma unroll
            for (int f = 0; f < 8; f++) {
                #pragma unroll
                for (int e = 0; e < 4; e++) {
                    int col = f*8 + tg*2 + (e & 1);
                    int row = wrp*16 + g + ((e >> 1) ? 8 : 0);
                    if (col > row) sv[f][e] = -1e30f;
                }
            }
        }

        // ---- online softmax ----
        float rm0 = -1e30f, rm1 = -1e30f;
        #pragma unroll
        for (int f = 0; f < 8; f++) {
            rm0 = fmaxf(rm0, fmaxf(sv[f][0], sv[f][1]));
            rm1 = fmaxf(rm1, fmaxf(sv[f][2], sv[f][3]));
        }
        rm0 = fmaxf(rm0, __shfl_xor_sync(0xffffffffu, rm0, 1));
        rm0 = fmaxf(rm0, __shfl_xor_sync(0xffffffffu, rm0, 2));
        rm1 = fmaxf(rm1, __shfl_xor_sync(0xffffffffu, rm1, 1));
        rm1 = fmaxf(rm1, __shfl_xor_sync(0xffffffffu, rm1, 2));
        const float mn0 = fmaxf(m0, rm0), mn1 = fmaxf(m1, rm1);
        const float c0 = __expf(m0 - mn0), c1 = __expf(m1 - mn1);
        float ls0 = 0.f, ls1 = 0.f;
        #pragma unroll
        for (int f = 0; f < 8; f++) {
            sv[f][0] = __expf(sv[f][0] - mn0);
            sv[f][1] = __expf(sv[f][1] - mn0);
            sv[f][2] = __expf(sv[f][2] - mn1);
            sv[f][3] = __expf(sv[f][3] - mn1);
            ls0 += sv[f][0] + sv[f][1];
            ls1 += sv[f][2] + sv[f][3];
        }
        ls0 += __shfl_xor_sync(0xffffffffu, ls0, 1);
        ls0 += __shfl_xor_sync(0xffffffffu, ls0, 2);
        ls1 += __shfl_xor_sync(0xffffffffu, ls1, 1);
        ls1 += __shfl_xor_sync(0xffffffffu, ls1, 2);
        l0 = l0*c0 + ls0; l1 = l1*c1 + ls1;
        m0 = mn0; m1 = mn1;
        #pragma unroll
        for (int f = 0; f < 16; f++) {
            o[f][0] *= c0; o[f][1] *= c0;
            o[f][2] *= c1; o[f][3] *= c1;
        }

        // ---- O += P @ V ----
        #pragma unroll
        for (int kk = 0; kk < 4; kk++) {
            uint32_t ah[4], al[4];
            ah[0] = pack_hi2(sv[2*kk][0],   sv[2*kk][1]);
            ah[1] = pack_hi2(sv[2*kk][2],   sv[2*kk][3]);
            ah[2] = pack_hi2(sv[2*kk+1][0], sv[2*kk+1][1]);
            ah[3] = pack_hi2(sv[2*kk+1][2], sv[2*kk+1][3]);
            al[0] = pack_lo2(sv[2*kk][0],   sv[2*kk][1]);
            al[1] = pack_lo2(sv[2*kk][2],   sv[2*kk][3]);
            al[2] = pack_lo2(sv[2*kk+1][0], sv[2*kk+1][1]);
            al[3] = pack_lo2(sv[2*kk+1][2], sv[2*kk+1][3]);
            #pragma unroll
            for (int fp = 0; fp < 8; fp++) {
                uint32_t bh[4], bl[4];
                const int brow = kk*16 + (lane & 7) + ((lane >> 3) & 1) * 8;
                const int bcol = fp*16 + ((lane >> 4) & 1) * 8;
                ldm_x4_t(bh, vh + brow*136 + bcol);
                ldm_x4_t(bl, vl + brow*136 + bcol);
                mma16816(o[2*fp],   ah, &bh[0]);
                mma16816(o[2*fp],   ah, &bl[0]);
                mma16816(o[2*fp],   al, &bh[0]);
                mma16816(o[2*fp+1], ah, &bh[2]);
                mma16816(o[2*fp+1], ah, &bl[2]);
                mma16816(o[2*fp+1], al, &bh[2]);
            }
        }
        __syncthreads();
    }

    // ---- epilogue ----
    const float inv0 = 1.0f / l0, inv1 = 1.0f / l1;
    const size_t row0 = (size_t)b*T_ + q0 + wrp*16 + g;
    const size_t row1 = row0 + 8;
    #pragma unroll
    for (int f = 0; f < 16; f++) {
        const int col = f*8 + tg*2;
        float2 v0 = make_float2(o[f][0]*inv0, o[f][1]*inv0);
        float2 v1 = make_float2(o[f][2]*inv1, o[f][3]*inv1);
        *reinterpret_cast<float2*>(out + row0*H_ + col) = v0;
        *reinterpret_cast<float2*>(out + row1*H_ + col) = v1;
    }
}

extern "C" void kernel_launch(void* const* d_in, const int* in_sizes, int n_in,
                              void* d_out, int out_size)
{
    const float* x  = (const float*)d_in[0];
    const float* Wq = (const float*)d_in[1];
    const float* Wk = (const float*)d_in[2];
    const float* Wv = (const float*)d_in[3];
    float* out = (float*)d_out;

    const int proj_smem = (4*PX_ + 4*PW_) * (int)sizeof(__nv_bfloat16);   // 106496
    const int attn_smem = 10*AT_ * (int)sizeof(__nv_bfloat16);            // 174080
    cudaFuncSetAttribute(proj_mma, cudaFuncAttributeMaxDynamicSharedMemorySize, proj_smem);
    cudaFuncSetAttribute(attn_mma, cudaFuncAttributeMaxDynamicSharedMemorySize, attn_smem);

    split_x_kernel<<<BT_*E_/4/256, 256>>>(x);
    split_w_kernel<<<dim3(E_*H_/4/256, 3), 256>>>(Wq, Wk, Wv);
    proj_mma<<<dim3(BT_/64, 3), 128, proj_smem>>>();
    attn_mma<<<dim3(T_/64, B_), 128, attn_smem>>>(out);
}